// round 1
// baseline (speedup 1.0000x reference)
#include <cuda_runtime.h>
#include <cstdint>

// KVGather: out[n,i,k,w,c] = r_weight[n,i,k] * kv[n, r_idx[n,i,k], w, c]
// N=16, P2=64, TOPK=8, W2=64, C_KV=512
// Output: 16*64*8*64*512 fp32 = 1 GiB  -> pure HBM-write-bound stream.
// kv: 128 MiB; per-n working set 8 MiB -> gather reads mostly hit L2.

#define KVG_N     16
#define KVG_P2    64
#define KVG_TOPK  8
#define KVG_W2    64
#define KVG_CKV   512

#define NUM_TILES   (KVG_N * KVG_P2 * KVG_TOPK)      // 8192
#define TILE_F4     (KVG_W2 * KVG_CKV / 4)           // 8192 float4 per tile (128 KB)
#define F4_PER_THR  8
#define THREADS     256
#define F4_PER_BLK  (F4_PER_THR * THREADS)           // 2048
#define BLKS_PER_TILE (TILE_F4 / F4_PER_BLK)         // 4
#define GRID        (NUM_TILES * BLKS_PER_TILE)      // 32768

// Flag: 1 if r_idx buffer is int64, 0 if int32. Written by detect kernel
// before every gather launch (same stream -> ordered, deterministic).
__device__ int g_idx_is64;

// If the buffer holds 8192 int64 values in [0,64), then viewed as int32 words
// every odd word is zero. If it holds 8192 int32 values, the odd words are
// real indices (uniform in [0,64)) and the OR over 4096 of them is nonzero
// with probability 1 - (1/64)^4096 ~ 1. Reading word index up to 8191 is
// in-bounds for both layouts (int32 layout has exactly 8192 words).
__global__ void kvg_detect_idx_width(const int* __restrict__ ridx32) {
    __shared__ int s_or;
    if (threadIdx.x == 0) s_or = 0;
    __syncthreads();
    int acc = 0;
    for (int i = threadIdx.x; i < NUM_TILES / 2; i += blockDim.x)
        acc |= ridx32[2 * i + 1];
    atomicOr(&s_or, acc);
    __syncthreads();
    if (threadIdx.x == 0) g_idx_is64 = (s_or == 0) ? 1 : 0;
}

__global__ __launch_bounds__(THREADS, 8)
void kvg_gather_kernel(const float4* __restrict__ kv,
                       const float*  __restrict__ r_weight,
                       const void*   __restrict__ r_idx,
                       float4*       __restrict__ out) {
    const int bid   = blockIdx.x;
    const int tile  = bid >> 2;            // BLKS_PER_TILE = 4
    const int chunk = bid & 3;
    const int n     = tile >> 9;           // / (P2*TOPK)

    // Region index (uniform per tile; branch on uniform flag is cheap)
    long long idx;
    if (g_idx_is64) {
        idx = ((const long long*)r_idx)[tile];
    } else {
        idx = (long long)((const int*)r_idx)[tile];
    }
    const float wt = r_weight[tile];

    const float4* __restrict__ src =
        kv + ((long long)n * KVG_P2 + idx) * (long long)TILE_F4;
    float4* __restrict__ dst = out + (long long)tile * (long long)TILE_F4;

    const int base = chunk * F4_PER_BLK + threadIdx.x;

#pragma unroll
    for (int j = 0; j < F4_PER_THR; j++) {
        const int p = base + j * THREADS;
        float4 v = __ldg(&src[p]);
        v.x *= wt; v.y *= wt; v.z *= wt; v.w *= wt;
        // Streaming store: the 1 GiB write stream is write-once; mark it
        // evict-first so the hot 8 MiB kv region stays resident in L2.
        __stcs(&dst[p], v);
    }
}

extern "C" void kernel_launch(void* const* d_in, const int* in_sizes, int n_in,
                              void* d_out, int out_size) {
    // metadata order: r_idx, r_weight, kv
    const void*  r_idx    = d_in[0];
    const float* r_weight = (const float*)d_in[1];
    const float4* kv      = (const float4*)d_in[2];
    float4* out           = (float4*)d_out;

    kvg_detect_idx_width<<<1, 256>>>((const int*)r_idx);
    kvg_gather_kernel<<<GRID, THREADS>>>(kv, r_weight, r_idx, out);
}